// round 17
// baseline (speedup 1.0000x reference)
#include <cuda_runtime.h>
#include <cuda_fp16.h>

// GraphSAGE 2-layer, N=100000, E=1600000, dims 32 -> 64 -> 32.
//   K0: prep    zero g_aggh + g_agg2h (fp16) + convert x -> xh (fp16)
//   K1: scatter g_aggh[dst] += xh[src]     (4 thr/edge, v4.f16x2 RED = 8 halves/op)
//   K2: fused block-tiled GEMM MLP (128 nodes/block, 8x8 tiles, FFMA2);
//       agg read fp16, x fp32; writes g as fp16 (g_gh), r as fp32 (out)
//   K3: scatter g_agg2h[dst] += g_gh[src]  (4 thr/edge, v4.f16x2 RED)
//   K4: finalize out += float(g_agg2h)
// Layer-2 projection applied BEFORE the scatter (linear commutes with sum).
// edge_index is int32 on device.

#define MAX_NODES 100000
#define D 32

typedef unsigned long long ull;

__device__ __half g_aggh[MAX_NODES * D];    // layer-1 fp16 aggregation
__device__ __half g_xh[MAX_NODES * D];      // fp16 copy of x
__device__ __half g_gh[MAX_NODES * D];      // fp16 projected h (layer-2 payload)
__device__ __half g_agg2h[MAX_NODES * D];   // layer-2 fp16 aggregation

__device__ __forceinline__ void red_add_v4h2(__half* addr, uint4 v) {
    asm volatile("red.global.add.noftz.v4.f16x2 [%0], {%1, %2, %3, %4};"
                 :: "l"(addr), "r"(v.x), "r"(v.y), "r"(v.z), "r"(v.w)
                 : "memory");
}
__device__ __forceinline__ ull fma2(ull a, ull b, ull c) {
    ull d;
    asm("fma.rn.f32x2 %0, %1, %2, %3;" : "=l"(d) : "l"(a), "l"(b), "l"(c));
    return d;
}
__device__ __forceinline__ ull pack2(float lo, float hi) {
    ull d;
    asm("mov.b64 %0, {%1, %2};" : "=l"(d) : "f"(lo), "f"(hi));
    return d;
}
__device__ __forceinline__ ull pack2s(float v) {
    ull d;
    asm("mov.b64 %0, {%1, %1};" : "=l"(d) : "f"(v));
    return d;
}
__device__ __forceinline__ void unpack2(ull v, float& lo, float& hi) {
    asm("mov.b64 {%0, %1}, %2;" : "=f"(lo), "=f"(hi) : "l"(v));
}

// ---------------------------------------------------------------------------
// prep: zero both fp16 agg buffers, convert x -> xh. Unit = 8 halves.
__global__ void prep_kernel(const float* __restrict__ x, int n8) {
    int i = blockIdx.x * blockDim.x + threadIdx.x;
    if (i >= n8) return;
    ((uint4*)g_aggh)[i]  = make_uint4(0u, 0u, 0u, 0u);
    ((uint4*)g_agg2h)[i] = make_uint4(0u, 0u, 0u, 0u);
    const float4* xp = (const float4*)x;
    float4 a = __ldg(&xp[2 * i]);
    float4 b = __ldg(&xp[2 * i + 1]);
    __half2 h0 = __floats2half2_rn(a.x, a.y);
    __half2 h1 = __floats2half2_rn(a.z, a.w);
    __half2 h2 = __floats2half2_rn(b.x, b.y);
    __half2 h3 = __floats2half2_rn(b.z, b.w);
    uint4 o;
    o.x = *(unsigned*)&h0; o.y = *(unsigned*)&h1;
    o.z = *(unsigned*)&h2; o.w = *(unsigned*)&h3;
    ((uint4*)g_xh)[i] = o;
}

// ---------------------------------------------------------------------------
// fp16 scatter: 4 threads/edge, thread q handles halves [8q, 8q+8).
__global__ void scatter_x_kernel(const int* __restrict__ src,
                                 const int* __restrict__ dst,
                                 int E) {
    int t = blockIdx.x * blockDim.x + threadIdx.x;
    int e = t >> 2;
    int q = (t & 3) << 3;
    if (e >= E) return;
    int s = __ldg(&src[e]);
    int d = __ldg(&dst[e]);
    uint4 v = __ldg((const uint4*)&g_xh[s * D + q]);
    red_add_v4h2(&g_aggh[d * D + q], v);
}

__global__ void scatter_g_kernel(const int* __restrict__ src,
                                 const int* __restrict__ dst,
                                 int E) {
    int t = blockIdx.x * blockDim.x + threadIdx.x;
    int e = t >> 2;
    int q = (t & 3) << 3;
    if (e >= E) return;
    int s = __ldg(&src[e]);
    int d = __ldg(&dst[e]);
    uint4 v = __ldg((const uint4*)&g_gh[s * D + q]);
    red_add_v4h2(&g_agg2h[d * D + q], v);
}

// ---------------------------------------------------------------------------
// finalize: out += float(g_agg2h). Unit = 8 elements.
__global__ void finalize_kernel(float* __restrict__ out, int n8) {
    int i = blockIdx.x * blockDim.x + threadIdx.x;
    if (i >= n8) return;
    uint4 u = ((const uint4*)g_agg2h)[i];
    float2 f0 = __half22float2(*(__half2*)&u.x);
    float2 f1 = __half22float2(*(__half2*)&u.y);
    float2 f2 = __half22float2(*(__half2*)&u.z);
    float2 f3 = __half22float2(*(__half2*)&u.w);
    float4* o = (float4*)out + 2 * i;
    float4 a = o[0], b = o[1];
    a.x += f0.x; a.y += f0.y; a.z += f1.x; a.w += f1.y;
    b.x += f2.x; b.y += f2.y; b.z += f3.x; b.w += f3.y;
    o[0] = a; o[1] = b;
}

// ---------------------------------------------------------------------------
// Fused GEMM MLP. Block = 128 threads = 128 nodes. Thread tile: 8 nodes x 8 outs.
#define AT_PITCH 132
#define SM_AT    0
#define SM_W1    (64 * AT_PITCH * 4)
#define SM_W2    (SM_W1 + 64 * 32 * 8)
#define SM_B1    (SM_W2 + 64 * 32 * 8)
#define SM_B2    (SM_B1 + 32 * 8)
#define SM_TOTAL (SM_B2 + 32 * 8)                    // 67072

__global__ void __launch_bounds__(128)
gemm_mlp_kernel(const float* __restrict__ x,
                const float* __restrict__ Wli,  // [64,32]
                const float* __restrict__ bli,  // [64]
                const float* __restrict__ Wri,  // [64,32]
                const float* __restrict__ Wlo,  // [32,64]
                const float* __restrict__ blo,  // [32]
                const float* __restrict__ Wro,  // [32,64]
                float* __restrict__ out,
                int N) {
    extern __shared__ char sm[];
    float* At = (float*)(sm + SM_AT);
    ull* w1   = (ull*)(sm + SM_W1);
    ull* w2   = (ull*)(sm + SM_W2);
    ull* b1p  = (ull*)(sm + SM_B1);
    ull* b2p  = (ull*)(sm + SM_B2);

    int tid = threadIdx.x;

    // ---- stage weights (k-fastest -> coalesced) ----
    for (int i = tid; i < 2048; i += 128) {
        int k = i & 63, m2 = i >> 6;
        int m0 = 2 * m2, m1 = 2 * m2 + 1;
        float a0 = (k < 32) ? Wli[m0 * 32 + k] : Wri[m0 * 32 + k - 32];
        float a1 = (k < 32) ? Wli[m1 * 32 + k] : Wri[m1 * 32 + k - 32];
        w1[k * 32 + m2] = pack2(a0, a1);
        float c0 = (m0 < 32) ? Wlo[m0 * 64 + k] : Wro[(m0 - 32) * 64 + k];
        float c1 = (m1 < 32) ? Wlo[m1 * 64 + k] : Wro[(m1 - 32) * 64 + k];
        w2[k * 32 + m2] = pack2(c0, c1);
    }
    if (tid < 32) {
        b1p[tid] = pack2(bli[2 * tid], bli[2 * tid + 1]);
        b2p[tid] = (tid < 16) ? 0ull
                              : pack2(blo[2 * tid - 32], blo[2 * tid - 31]);
    }

    // ---- stage inputs transposed: At[k][node]; agg from fp16, x fp32 ----
    {
        int node = blockIdx.x * 128 + tid;
        if (node < N) {
            const uint4* ar = (const uint4*)&g_aggh[node * D];
            const float4* xr = (const float4*)&x[node * D];
            #pragma unroll
            for (int c = 0; c < 4; c++) {
                uint4 u = __ldg(&ar[c]);
                float2 f0 = __half22float2(*(__half2*)&u.x);
                float2 f1 = __half22float2(*(__half2*)&u.y);
                float2 f2 = __half22float2(*(__half2*)&u.z);
                float2 f3 = __half22float2(*(__half2*)&u.w);
                At[(8 * c + 0) * AT_PITCH + tid] = f0.x;
                At[(8 * c + 1) * AT_PITCH + tid] = f0.y;
                At[(8 * c + 2) * AT_PITCH + tid] = f1.x;
                At[(8 * c + 3) * AT_PITCH + tid] = f1.y;
                At[(8 * c + 4) * AT_PITCH + tid] = f2.x;
                At[(8 * c + 5) * AT_PITCH + tid] = f2.y;
                At[(8 * c + 6) * AT_PITCH + tid] = f3.x;
                At[(8 * c + 7) * AT_PITCH + tid] = f3.y;
            }
            #pragma unroll
            for (int c = 0; c < 8; c++) {
                float4 v = __ldg(&xr[c]);
                At[(32 + 4 * c + 0) * AT_PITCH + tid] = v.x;
                At[(32 + 4 * c + 1) * AT_PITCH + tid] = v.y;
                At[(32 + 4 * c + 2) * AT_PITCH + tid] = v.z;
                At[(32 + 4 * c + 3) * AT_PITCH + tid] = v.w;
            }
        } else {
            #pragma unroll
            for (int k = 0; k < 64; k++) At[k * AT_PITCH + tid] = 0.0f;
        }
    }
    __syncthreads();

    int n8 = tid & 15;
    int o8 = tid >> 4;

    // ---- stage 1: h = relu(W1 @ A + b1) ----
    ull acc[8][4];
    #pragma unroll
    for (int n = 0; n < 8; n++)
        #pragma unroll
        for (int j = 0; j < 4; j++) acc[n][j] = b1p[o8 * 4 + j];

    #pragma unroll 4
    for (int k = 0; k < 64; k++) {
        const float* arow = &At[k * AT_PITCH + n8 * 8];
        float4 a0 = *(const float4*)arow;
        float4 a1 = *(const float4*)(arow + 4);
        ull ap[8];
        ap[0] = pack2s(a0.x); ap[1] = pack2s(a0.y);
        ap[2] = pack2s(a0.z); ap[3] = pack2s(a0.w);
        ap[4] = pack2s(a1.x); ap[5] = pack2s(a1.y);
        ap[6] = pack2s(a1.z); ap[7] = pack2s(a1.w);
        const ull* wrow = &w1[k * 32 + o8 * 4];
        ull wv0 = wrow[0], wv1 = wrow[1], wv2 = wrow[2], wv3 = wrow[3];
        #pragma unroll
        for (int n = 0; n < 8; n++) {
            acc[n][0] = fma2(ap[n], wv0, acc[n][0]);
            acc[n][1] = fma2(ap[n], wv1, acc[n][1]);
            acc[n][2] = fma2(ap[n], wv2, acc[n][2]);
            acc[n][3] = fma2(ap[n], wv3, acc[n][3]);
        }
    }

    __syncthreads();

    // relu + write h_t[k=output][node]
    #pragma unroll
    for (int n = 0; n < 8; n++) {
        #pragma unroll
        for (int j = 0; j < 4; j++) {
            float lo, hi;
            unpack2(acc[n][j], lo, hi);
            At[(o8 * 8 + 2 * j)     * AT_PITCH + n8 * 8 + n] = fmaxf(lo, 0.0f);
            At[(o8 * 8 + 2 * j + 1) * AT_PITCH + n8 * 8 + n] = fmaxf(hi, 0.0f);
        }
    }
    __syncthreads();

    // ---- stage 2: [g|r] = W2 @ h (+ bias) ----
    #pragma unroll
    for (int n = 0; n < 8; n++)
        #pragma unroll
        for (int j = 0; j < 4; j++) acc[n][j] = b2p[o8 * 4 + j];

    #pragma unroll 4
    for (int k = 0; k < 64; k++) {
        const float* arow = &At[k * AT_PITCH + n8 * 8];
        float4 a0 = *(const float4*)arow;
        float4 a1 = *(const float4*)(arow + 4);
        ull ap[8];
        ap[0] = pack2s(a0.x); ap[1] = pack2s(a0.y);
        ap[2] = pack2s(a0.z); ap[3] = pack2s(a0.w);
        ap[4] = pack2s(a1.x); ap[5] = pack2s(a1.y);
        ap[6] = pack2s(a1.z); ap[7] = pack2s(a1.w);
        const ull* wrow = &w2[k * 32 + o8 * 4];
        ull wv0 = wrow[0], wv1 = wrow[1], wv2 = wrow[2], wv3 = wrow[3];
        #pragma unroll
        for (int n = 0; n < 8; n++) {
            acc[n][0] = fma2(ap[n], wv0, acc[n][0]);
            acc[n][1] = fma2(ap[n], wv1, acc[n][1]);
            acc[n][2] = fma2(ap[n], wv2, acc[n][2]);
            acc[n][3] = fma2(ap[n], wv3, acc[n][3]);
        }
    }

    // ---- write: o8<4 -> g_gh (fp16), o8>=4 -> out (fp32) ----
    int nbase = blockIdx.x * 128 + n8 * 8;
    #pragma unroll
    for (int n = 0; n < 8; n++) {
        int node = nbase + n;
        if (node >= N) break;
        float l0, h0, l1, h1, l2, h2, l3, h3;
        unpack2(acc[n][0], l0, h0);
        unpack2(acc[n][1], l1, h1);
        unpack2(acc[n][2], l2, h2);
        unpack2(acc[n][3], l3, h3);
        if (o8 < 4) {
            __half2 p0 = __floats2half2_rn(l0, h0);
            __half2 p1 = __floats2half2_rn(l1, h1);
            __half2 p2 = __floats2half2_rn(l2, h2);
            __half2 p3 = __floats2half2_rn(l3, h3);
            uint4 u;
            u.x = *(unsigned*)&p0; u.y = *(unsigned*)&p1;
            u.z = *(unsigned*)&p2; u.w = *(unsigned*)&p3;
            *(uint4*)&g_gh[node * D + o8 * 8] = u;
        } else {
            float* p = &out[node * D + (o8 - 4) * 8];
            *(float4*)p = make_float4(l0, h0, l1, h1);
            *(float4*)(p + 4) = make_float4(l2, h2, l3, h3);
        }
    }
}

// ---------------------------------------------------------------------------
extern "C" void kernel_launch(void* const* d_in, const int* in_sizes, int n_in,
                              void* d_out, int out_size) {
    const float* x   = (const float*)d_in[0];
    const int*   ei  = (const int*)d_in[1];
    const float* Wli = (const float*)d_in[2];
    const float* bli = (const float*)d_in[3];
    const float* Wri = (const float*)d_in[4];
    const float* Wlo = (const float*)d_in[5];
    const float* blo = (const float*)d_in[6];
    const float* Wro = (const float*)d_in[7];
    float* out = (float*)d_out;

    int N = in_sizes[0] / D;      // 100000
    int E = in_sizes[1] / 2;      // 1600000
    const int* src = ei;
    const int* dst = ei + E;

    static bool attr_set = false;
    if (!attr_set) {
        cudaFuncSetAttribute(gemm_mlp_kernel,
                             cudaFuncAttributeMaxDynamicSharedMemorySize,
                             SM_TOTAL);
        attr_set = true;
    }

    int n8 = N * D / 8;
    {   // K0: zero fp16 agg buffers + convert x -> fp16
        prep_kernel<<<(n8 + 255) / 256, 256>>>(x, n8);
    }
    {   // K1: layer-1 scatter (fp16x2 REDs)
        int blocks = (E + 63) / 64;
        scatter_x_kernel<<<blocks, 256>>>(src, dst, E);
    }
    {   // K2: fused GEMM MLP
        int blocks = (N + 127) / 128;
        gemm_mlp_kernel<<<blocks, 128, SM_TOTAL>>>(x, Wli, bli, Wri,
                                                   Wlo, blo, Wro, out, N);
    }
    {   // K3: layer-2 scatter (fp16x2 REDs)
        int blocks = (E + 63) / 64;
        scatter_g_kernel<<<blocks, 256>>>(src, dst, E);
    }
    {   // K4: out += float(g_agg2h)
        finalize_kernel<<<(n8 + 255) / 256, 256>>>(out, n8);
    }
}